// round 13
// baseline (speedup 1.0000x reference)
#include <cuda_runtime.h>
#include <cuda_fp16.h>

// ============================================================================
// Problem constants
// ============================================================================
static constexpr int N_NODES  = 10000;
static constexpr int N_EDGES  = 250000;
static constexpr int FEAT     = 288;   // 9 * F
static constexpr int F        = 32;
static constexpr int HIDDEN   = 64;
static constexpr int NPATH    = 11;
static constexpr int RADIAL   = NPATH * F;       // 352
static constexpr int EPB      = 32;              // edges per block
static constexpr int NBLK     = (N_EDGES + EPB - 1) / EPB;   // 7813
static constexpr int NTILES_N = RADIAL / 8;      // 44 n-tiles of 8 cols
static constexpr int NKS      = HIDDEN / 16;     // 4 k-tiles of 16
static constexpr int RSL_W    = 1608;            // per-warp rsl stride (floats); 1608%32==8
static constexpr int HSTRIDE  = 72;              // halves per h_s row (144 B, 4B-aligned)

// __device__ scratch (static; no runtime allocation)
__device__ uint2 d_w2h[NKS * NTILES_N * 32];     // fp16 fragment-ordered w2
__device__ float d_b2p[RADIAL];                  // b2 permuted: col' = u*11 + t

// ============================================================================
// Compile-time Wigner-3j construction (faithful port of the reference numpy)
// ============================================================================
#define HDC __host__ __device__ constexpr

HDC double cfact(int n) { double r = 1.0; for (int i = 2; i <= n; ++i) r *= (double)i; return r; }

HDC double csqrt(double x) {
    if (x <= 0.0) return 0.0;
    double g = (x > 1.0) ? x : 1.0;
    for (int i = 0; i < 40; ++i) g = 0.5 * (g + x / g);
    return g;
}

HDC double su2_cg(int j1, int j2, int j3, int m1, int m2, int m3) {
    if (m1 + m2 != m3) return 0.0;
    double pref = csqrt((2.0 * j3 + 1.0) * cfact(j1 + j2 - j3) * cfact(j1 - j2 + j3) *
                        cfact(-j1 + j2 + j3) / cfact(j1 + j2 + j3 + 1));
    pref *= csqrt(cfact(j3 + m3) * cfact(j3 - m3) * cfact(j1 - m1) * cfact(j1 + m1) *
                  cfact(j2 - m2) * cfact(j2 + m2));
    double s = 0.0;
    for (int k = 0; k <= j1 + j2 - j3; ++k) {
        int d0 = k, d1 = j1 + j2 - j3 - k, d2 = j1 - m1 - k, d3 = j2 + m2 - k;
        int d4 = j3 - j2 + m1 + k, d5 = j3 - j1 - m2 + k;
        if (d0 < 0 || d1 < 0 || d2 < 0 || d3 < 0 || d4 < 0 || d5 < 0) continue;
        double term = 1.0 / (cfact(d0) * cfact(d1) * cfact(d2) * cfact(d3) * cfact(d4) * cfact(d5));
        s += (k & 1) ? -term : term;
    }
    return pref * s;
}

struct CD { double re, im; };
HDC CD cmul(CD a, CD b) { return CD{a.re * b.re - a.im * b.im, a.re * b.im + a.im * b.re}; }

struct Qm { CD v[5][5]; };
HDC Qm qmat(int l) {
    Qm q{};
    for (int i = 0; i < 5; ++i) for (int j = 0; j < 5; ++j) q.v[i][j] = CD{0.0, 0.0};
    const double inv = 1.0 / csqrt(2.0);
    for (int m = -l; m < 0; ++m) {
        q.v[l + m][l - m] = CD{inv, 0.0};
        q.v[l + m][l + m] = CD{0.0, -inv};
    }
    q.v[l][l] = CD{1.0, 0.0};
    for (int m = 1; m <= l; ++m) {
        const double sgn = (m & 1) ? -1.0 : 1.0;
        q.v[l + m][l + m] = CD{sgn * inv, 0.0};
        q.v[l + m][l - m] = CD{0.0, sgn * inv};
    }
    const CD ph = (l == 0) ? CD{1.0, 0.0} : ((l == 1) ? CD{0.0, -1.0} : CD{-1.0, 0.0}); // (-i)^l
    for (int i = 0; i < 2 * l + 1; ++i)
        for (int j = 0; j < 2 * l + 1; ++j) q.v[i][j] = cmul(ph, q.v[i][j]);
    return q;
}

HDC double path_pref(int p) {
    const int k = (p == 0 || p == 4 || p == 9) ? 0 : ((p == 1 || p == 3 || p == 6 || p == 8) ? 1 : 2);
    const double cnt = (k == 0) ? 3.0 : 4.0;
    return csqrt((2.0 * k + 1.0) / cnt) * 0.2;
}

struct W3 { double v[5][5][5]; };
HDC W3 w3j_calc(int l1, int l2, int l3, int p) {
    W3 out{};
    double C[5][5][5] = {};
    for (int m1 = -l1; m1 <= l1; ++m1)
        for (int m2 = -l2; m2 <= l2; ++m2)
            for (int m3 = -l3; m3 <= l3; ++m3)
                C[l1 + m1][l2 + m2][l3 + m3] = su2_cg(l1, l2, l3, m1, m2, m3);
    const Qm q1 = qmat(l1), q2 = qmat(l2), q3 = qmat(l3);
    const int d1 = 2 * l1 + 1, d2 = 2 * l2 + 1, d3 = 2 * l3 + 1;
    double Wr[5][5][5] = {}, Wi[5][5][5] = {};
    for (int j = 0; j < d1; ++j)
        for (int l = 0; l < d2; ++l)
            for (int n = 0; n < d3; ++n) {
                CD acc{0.0, 0.0};
                for (int i = 0; i < d1; ++i)
                    for (int k = 0; k < d2; ++k)
                        for (int m = 0; m < d3; ++m) {
                            const double c = C[i][k][m];
                            if (c == 0.0) continue;
                            CD t = cmul(q1.v[i][j], q2.v[k][l]);
                            t = cmul(t, CD{q3.v[m][n].re, -q3.v[m][n].im});
                            acc.re += t.re * c;
                            acc.im += t.im * c;
                        }
                Wr[j][l][n] = acc.re;
                Wi[j][l][n] = acc.im;
            }
    double nr = 0.0, ni = 0.0;
    for (int j = 0; j < d1; ++j)
        for (int l = 0; l < d2; ++l)
            for (int n = 0; n < d3; ++n) { nr += Wr[j][l][n] * Wr[j][l][n]; ni += Wi[j][l][n] * Wi[j][l][n]; }
    const bool useR = (nr >= ni);
    const double scale = path_pref(p) / csqrt(useR ? nr : ni);
    for (int j = 0; j < d1; ++j)
        for (int l = 0; l < d2; ++l)
            for (int n = 0; n < d3; ++n)
                out.v[j][l][n] = (useR ? Wr[j][l][n] : Wi[j][l][n]) * scale;
    return out;
}

template <int I, int J, int K, int P>
struct WHold { static constexpr W3 W = w3j_calc(I, J, K, P); };
template <int I, int J, int K, int P> constexpr W3 WHold<I, J, K, P>::W;

template <int N> struct Ic { static constexpr int v = N; };

template <int NA, int NB, int NC, int IDX, class Fn>
__device__ __forceinline__ void unr3(Fn&& f) {
    if constexpr (IDX < NA * NB * NC) {
        f(Ic<IDX / (NB * NC)>{}, Ic<(IDX / NC) % NB>{}, Ic<IDX % NC>{});
        unr3<NA, NB, NC, IDX + 1>(f);
    }
}

template <int I, int J, int K, int P>
__device__ __forceinline__ void apply_path(const float (&xi)[2 * I + 1],
                                           const float (&yj)[2 * J + 1],
                                           float rw,
                                           float (&ok)[2 * K + 1]) {
    unr3<2 * I + 1, 2 * J + 1, 2 * K + 1, 0>([&](auto A, auto B, auto C) {
        constexpr double wv = WHold<I, J, K, P>::W.v[decltype(A)::v][decltype(B)::v][decltype(C)::v];
        if constexpr (wv > 1e-7 || wv < -1e-7) {
            ok[decltype(C)::v] =
                fmaf((float)wv * (xi[decltype(A)::v] * yj[decltype(B)::v]), rw, ok[decltype(C)::v]);
        }
    });
}

__device__ __forceinline__ unsigned pack_half2(float lo, float hi) {
    const __half2 h = __floats2half2_rn(lo, hi);
    return *(const unsigned*)&h;
}

// ============================================================================
// Prep kernel: fp16 fragment-ordered, column-permuted copy of w2.
// ============================================================================
__global__ void prep_kernel(const float* __restrict__ w2, const float* __restrict__ b2) {
    const int idx = blockIdx.x * blockDim.x + threadIdx.x;
    if (idx < NKS * NTILES_N * 32) {
        const int l    = idx & 31;
        const int tile = idx >> 5;
        const int ks   = tile / NTILES_N;
        const int ntg  = tile % NTILES_N;
        const int tig  = l & 3;
        const int gid  = l >> 2;
        const int colp = ntg * 8 + gid;
        const int u    = colp / NPATH;
        const int t    = colp % NPATH;
        const int col  = t * F + u;
        const int k0   = ks * 16 + tig * 2;
        uint2 v;
        v.x = pack_half2(w2[(k0 + 0) * RADIAL + col], w2[(k0 + 1) * RADIAL + col]);
        v.y = pack_half2(w2[(k0 + 8) * RADIAL + col], w2[(k0 + 9) * RADIAL + col]);
        d_w2h[idx] = v;
    }
    if (idx < RADIAL) {
        const int u = idx / NPATH;
        const int t = idx % NPATH;
        d_b2p[idx] = b2[t * F + u];
    }
}

// ============================================================================
// Fused kernel: 32 edges/block, 128 threads, 6 blocks/SM.
//  P1: MLP -> h_s (fp16) + geom/meta
//  per 16-edge m-tile: [warps mma 88-col slices -> rsl] sync
//                      [warp w TP for 4 edges; gather+scatter staged via smem]
// ============================================================================
__global__ void __launch_bounds__(128, 6)
conv_kernel(const float* __restrict__ nodes, const float* __restrict__ pos,
            const int* __restrict__ src, const int* __restrict__ dst,
            const float* __restrict__ w1, const float* __restrict__ b1,
            float* __restrict__ out) {
    __shared__ __half h_s[EPB * HSTRIDE];   // [32][72] fp16           (4608 B)
    __shared__ float rsl[4 * RSL_W];        // 4 x (16x100 + 8 skew)  (25728 B)
    __shared__ float stg[4][296];           // per-warp staging buffer (4736 B)
    __shared__ float4 geom_s[EPB];          // (ux,uy,uz,cut)           (512 B)
    __shared__ int2  meta_s[EPB];           // (src,dst)                (256 B)
    __shared__ float b2p_s[RADIAL];         //                         (1408 B)

    const int tid  = threadIdx.x;
    const int lane = tid & 31;
    const int w    = tid >> 5;
    const int eblk = blockIdx.x * EPB;

    for (int i = tid; i < RADIAL; i += 128) b2p_s[i] = d_b2p[i];

    // ------------------------------------------------------------------ P1
    constexpr float PI = 3.14159265358979323846f;
    {
        float w1a[8], w1b[8];
#pragma unroll
        for (int n = 0; n < 8; ++n) {
            w1a[n] = w1[n * HIDDEN + lane];
            w1b[n] = w1[n * HIDDEN + 32 + lane];
        }
        const float b1a = b1[lane], b1b = b1[lane + 32];

        for (int i = 0; i < EPB / 4; ++i) {       // 8 edges per warp
            const int el = w * (EPB / 4) + i;
            const int eg = eblk + el;
            if (eg < N_EDGES) {
                const int s = src[eg], d = dst[eg];
                const float dx = pos[3 * s + 0] - pos[3 * d + 0];
                const float dy = pos[3 * s + 1] - pos[3 * d + 1];
                const float dz = pos[3 * s + 2] - pos[3 * d + 2];
                const float dist = sqrtf(dx * dx + dy * dy + dz * dz);

                const float uu = dist * 0.25f;
                const float uu2 = uu * uu;
                const float uu5 = uu2 * uu2 * uu;
                const float cutv = 1.0f - 6.0f * uu5 + 5.0f * uu5 * uu;
                const float cut = (dist < 4.0f) ? cutv : 0.0f;
                const float invd = __fdividef(1.0f, fmaxf(dist, 1e-12f));
                if (lane == 0) {
                    geom_s[el] = make_float4(dx * invd, dy * invd, dz * invd, cut);
                    meta_s[el] = make_int2(s, d);
                }

                const float t = dist * 0.2f;
                float sp, cp;
                __sincosf(PI * t, &sp, &cp);
                const float mask = (t > 0.0f && t < 1.0f) ? 1.0f : 0.0f;
                const float inv_t = (t > 0.0f) ? __fdividef(1.0f, t) : 1.0f;
                const float coef = 0.6324555320336759f * inv_t * mask;
                float acc_lo = b1a, acc_hi = b1b;
                float s_prev = 0.0f, s_cur = sp;
                const float c2 = 2.0f * cp;
#pragma unroll
                for (int n = 0; n < 8; ++n) {
                    const float bn = coef * s_cur;
                    acc_lo = fmaf(bn, w1a[n], acc_lo);
                    acc_hi = fmaf(bn, w1b[n], acc_hi);
                    const float s_next = c2 * s_cur - s_prev;
                    s_prev = s_cur; s_cur = s_next;
                }
                const float hlo = __fdividef(acc_lo, 1.0f + __expf(-acc_lo));
                const float hhi = __fdividef(acc_hi, 1.0f + __expf(-acc_hi));
                h_s[el * HSTRIDE + lane]      = __float2half_rn(hlo);
                h_s[el * HSTRIDE + 32 + lane] = __float2half_rn(hhi);
            } else {
                if (lane == 0) {
                    geom_s[el] = make_float4(0.f, 0.f, 0.f, 0.f);
                    meta_s[el] = make_int2(0, 0);
                }
                h_s[el * HSTRIDE + lane]      = __float2half_rn(0.f);
                h_s[el * HSTRIDE + 32 + lane] = __float2half_rn(0.f);
            }
        }
    }
    __syncthreads();

    // ------------------------------------------------------- per-m-tile loop
    const int gid = lane >> 2, tig = lane & 3;
    const uint2* __restrict__ bswz = d_w2h;
    constexpr float S3   = 1.7320508075688772f;
    constexpr float S15  = 3.8729833462074170f;
    constexpr float S5H  = 1.1180339887498949f;
    constexpr float S15H = 1.9364916731037085f;

#pragma unroll 1
    for (int mt = 0; mt < EPB / 16; ++mt) {       // 2 m-tiles
        // ---- mma: warp w -> cols 88w..88w+87 of rows mt*16..mt*16+15
        {
            float* rslw = rsl + w * RSL_W;
            const int r0 = mt * 16 + gid;
            unsigned afr[NKS][4];
#pragma unroll
            for (int ks = 0; ks < NKS; ++ks) {
                const int k0 = ks * 16 + tig * 2;
                afr[ks][0] = *(const unsigned*)&h_s[r0 * HSTRIDE + k0];
                afr[ks][1] = *(const unsigned*)&h_s[(r0 + 8) * HSTRIDE + k0];
                afr[ks][2] = *(const unsigned*)&h_s[r0 * HSTRIDE + k0 + 8];
                afr[ks][3] = *(const unsigned*)&h_s[(r0 + 8) * HSTRIDE + k0 + 8];
            }
#pragma unroll 1
            for (int nt = 0; nt < 11; ++nt) {
                const int ntg = 11 * w + nt;
                float d0 = 0.f, d1 = 0.f, d2 = 0.f, d3 = 0.f;
#pragma unroll
                for (int ks = 0; ks < NKS; ++ks) {
                    const uint2 bb = bswz[(ks * NTILES_N + ntg) * 32 + lane];  // coalesced 256B
                    asm volatile(
                        "mma.sync.aligned.m16n8k16.row.col.f32.f16.f16.f32 "
                        "{%0,%1,%2,%3}, {%4,%5,%6,%7}, {%8,%9}, {%0,%1,%2,%3};"
                        : "+f"(d0), "+f"(d1), "+f"(d2), "+f"(d3)
                        : "r"(afr[ks][0]), "r"(afr[ks][1]), "r"(afr[ks][2]), "r"(afr[ks][3]),
                          "r"(bb.x), "r"(bb.y));
                }
                const int c0 = nt * 8 + 2 * tig;
                *(float2*)&rslw[gid * 100 + c0]       = make_float2(d0, d1);
                *(float2*)&rslw[(gid + 8) * 100 + c0] = make_float2(d2, d3);
            }
        }
        __syncthreads();

        // ---- TP: warp w handles edges r = w*4..w*4+3; lane = channel u.
        //      Gather + scatter staged through per-warp smem (conflict-free).
        {
            const int uw = lane >> 3;               // source warp slice
            const int ubase = (lane & 7) * NPATH;   // col within slice
            float* sb = stg[w];
#pragma unroll 1
            for (int qq = 0; qq < 4; ++qq) {
                const int r  = w * 4 + qq;
                const int eg = eblk + mt * 16 + r;
                if (eg < N_EDGES) {
                    const float4 gm = geom_s[mt * 16 + r];
                    const int2 sd = meta_s[mt * 16 + r];
                    const float ux = gm.x, uy = gm.y, uz = gm.z, cut = gm.w;

                    // 1) cooperative coalesced gather of nodes row -> stg
                    {
                        const float4* nb4 = (const float4*)(nodes + (size_t)sd.x * FEAT);
                        float4* sb4 = (float4*)sb;
                        sb4[lane] = nb4[lane];
                        sb4[32 + lane] = nb4[32 + lane];
                        if (lane < 8) sb4[64 + lane] = nb4[64 + lane];
                    }
                    __syncwarp();

                    // 2) strided (conflict-free) reads into registers
                    float x0[1] = { sb[lane] };
                    float x1[3], x2[5];
#pragma unroll
                    for (int a = 0; a < 3; ++a) x1[a] = sb[32 + 3 * lane + a];
#pragma unroll
                    for (int a = 0; a < 5; ++a) x2[a] = sb[128 + 5 * lane + a];
                    __syncwarp();   // reads done before buffer reuse below

                    float y0[1] = { 1.0f };
                    float y1[3] = { S3 * uy, S3 * uz, S3 * ux };
                    float y2[5] = { S15 * ux * uy, S15 * uy * uz, S5H * (3.0f * uz * uz - 1.0f),
                                    S15 * ux * uz, S15H * (ux * ux - uy * uy) };

                    const float* rsrc = rsl + uw * RSL_W + r * 100 + ubase;
                    float rw[NPATH];
#pragma unroll
                    for (int t = 0; t < NPATH; ++t)
                        rw[t] = (rsrc[t] + b2p_s[lane * NPATH + t]) * cut;

                    float o0[1] = {0.0f};
                    float o1[3] = {0.0f, 0.0f, 0.0f};
                    float o2[5] = {0.0f, 0.0f, 0.0f, 0.0f, 0.0f};
                    apply_path<0, 0, 0, 0>(x0, y0, rw[0], o0);
                    apply_path<0, 1, 1, 1>(x0, y1, rw[1], o1);
                    apply_path<0, 2, 2, 2>(x0, y2, rw[2], o2);
                    apply_path<1, 0, 1, 3>(x1, y0, rw[3], o1);
                    apply_path<1, 1, 0, 4>(x1, y1, rw[4], o0);
                    apply_path<1, 1, 2, 5>(x1, y1, rw[5], o2);
                    apply_path<1, 2, 1, 6>(x1, y2, rw[6], o1);
                    apply_path<2, 0, 2, 7>(x2, y0, rw[7], o2);
                    apply_path<2, 1, 1, 8>(x2, y1, rw[8], o1);
                    apply_path<2, 2, 0, 9>(x2, y2, rw[9], o0);
                    apply_path<2, 2, 2, 10>(x2, y2, rw[10], o2);

                    // 3) transpose scatter: strided STS (conflict-free) ...
                    sb[lane] = o0[0];
#pragma unroll
                    for (int c = 0; c < 3; ++c) sb[32 + 3 * lane + c] = o1[c];
#pragma unroll
                    for (int c = 0; c < 5; ++c) sb[128 + 5 * lane + c] = o2[c];
                    __syncwarp();

                    // 4) ... then 9 coalesced single-line atomics
                    float* ob = out + (size_t)sd.y * FEAT;
#pragma unroll
                    for (int i = 0; i < 9; ++i)
                        atomicAdd(ob + i * 32 + lane, sb[i * 32 + lane]);
                    __syncwarp();   // buffer free before next qq gather
                }
            }
        }
        __syncthreads();   // rsl consumed before next tile's mma overwrites it
    }
}

// ============================================================================
// Launch: memset out, prep, fused kernel. All graph-capturable; no allocation.
// ============================================================================
extern "C" void kernel_launch(void* const* d_in, const int* in_sizes, int n_in,
                              void* d_out, int out_size) {
    (void)in_sizes; (void)n_in;
    const float* nodes = (const float*)d_in[0];
    const float* pos   = (const float*)d_in[1];
    const int*   src   = (const int*)d_in[2];
    const int*   dst   = (const int*)d_in[3];
    const float* w1    = (const float*)d_in[4];
    const float* b1    = (const float*)d_in[5];
    const float* w2    = (const float*)d_in[6];
    const float* b2    = (const float*)d_in[7];
    float* out = (float*)d_out;

    cudaMemsetAsync(out, 0, (size_t)out_size * sizeof(float), 0);

    const int prep_n = NKS * NTILES_N * 32;
    prep_kernel<<<(prep_n + 127) / 128, 128>>>(w2, b2);

    conv_kernel<<<NBLK, 128>>>(nodes, pos, src, dst, w1, b1, out);
}

// round 15
// speedup vs baseline: 1.2350x; 1.2350x over previous
#include <cuda_runtime.h>
#include <cuda_fp16.h>

// ============================================================================
// Problem constants
// ============================================================================
static constexpr int N_NODES  = 10000;
static constexpr int N_EDGES  = 250000;
static constexpr int FEAT     = 288;   // 9 * F
static constexpr int F        = 32;
static constexpr int HIDDEN   = 64;
static constexpr int NPATH    = 11;
static constexpr int RADIAL   = NPATH * F;       // 352
static constexpr int EPB      = 32;              // edges per block
static constexpr int NBLK     = (N_EDGES + EPB - 1) / EPB;   // 7813
static constexpr int NTILES_N = RADIAL / 8;      // 44 n-tiles of 8 cols
static constexpr int NKS      = HIDDEN / 16;     // 4 k-tiles of 16
static constexpr int RSL_W    = 1608;            // per-warp rsl stride (floats); 1608%32==8
static constexpr int HSTRIDE  = 72;              // halves per h_s row (144 B, 4B-aligned)

// __device__ scratch (static; no runtime allocation)
__device__ uint2 d_w2h[NKS * NTILES_N * 32];     // fp16 fragment-ordered w2
__device__ float d_b2p[RADIAL];                  // b2 permuted: col' = u*11 + t

// ============================================================================
// Compile-time Wigner-3j construction (faithful port of the reference numpy)
// ============================================================================
#define HDC __host__ __device__ constexpr

HDC double cfact(int n) { double r = 1.0; for (int i = 2; i <= n; ++i) r *= (double)i; return r; }

HDC double csqrt(double x) {
    if (x <= 0.0) return 0.0;
    double g = (x > 1.0) ? x : 1.0;
    for (int i = 0; i < 40; ++i) g = 0.5 * (g + x / g);
    return g;
}

HDC double su2_cg(int j1, int j2, int j3, int m1, int m2, int m3) {
    if (m1 + m2 != m3) return 0.0;
    double pref = csqrt((2.0 * j3 + 1.0) * cfact(j1 + j2 - j3) * cfact(j1 - j2 + j3) *
                        cfact(-j1 + j2 + j3) / cfact(j1 + j2 + j3 + 1));
    pref *= csqrt(cfact(j3 + m3) * cfact(j3 - m3) * cfact(j1 - m1) * cfact(j1 + m1) *
                  cfact(j2 - m2) * cfact(j2 + m2));
    double s = 0.0;
    for (int k = 0; k <= j1 + j2 - j3; ++k) {
        int d0 = k, d1 = j1 + j2 - j3 - k, d2 = j1 - m1 - k, d3 = j2 + m2 - k;
        int d4 = j3 - j2 + m1 + k, d5 = j3 - j1 - m2 + k;
        if (d0 < 0 || d1 < 0 || d2 < 0 || d3 < 0 || d4 < 0 || d5 < 0) continue;
        double term = 1.0 / (cfact(d0) * cfact(d1) * cfact(d2) * cfact(d3) * cfact(d4) * cfact(d5));
        s += (k & 1) ? -term : term;
    }
    return pref * s;
}

struct CD { double re, im; };
HDC CD cmul(CD a, CD b) { return CD{a.re * b.re - a.im * b.im, a.re * b.im + a.im * b.re}; }

struct Qm { CD v[5][5]; };
HDC Qm qmat(int l) {
    Qm q{};
    for (int i = 0; i < 5; ++i) for (int j = 0; j < 5; ++j) q.v[i][j] = CD{0.0, 0.0};
    const double inv = 1.0 / csqrt(2.0);
    for (int m = -l; m < 0; ++m) {
        q.v[l + m][l - m] = CD{inv, 0.0};
        q.v[l + m][l + m] = CD{0.0, -inv};
    }
    q.v[l][l] = CD{1.0, 0.0};
    for (int m = 1; m <= l; ++m) {
        const double sgn = (m & 1) ? -1.0 : 1.0;
        q.v[l + m][l + m] = CD{sgn * inv, 0.0};
        q.v[l + m][l - m] = CD{0.0, sgn * inv};
    }
    const CD ph = (l == 0) ? CD{1.0, 0.0} : ((l == 1) ? CD{0.0, -1.0} : CD{-1.0, 0.0}); // (-i)^l
    for (int i = 0; i < 2 * l + 1; ++i)
        for (int j = 0; j < 2 * l + 1; ++j) q.v[i][j] = cmul(ph, q.v[i][j]);
    return q;
}

HDC double path_pref(int p) {
    const int k = (p == 0 || p == 4 || p == 9) ? 0 : ((p == 1 || p == 3 || p == 6 || p == 8) ? 1 : 2);
    const double cnt = (k == 0) ? 3.0 : 4.0;
    return csqrt((2.0 * k + 1.0) / cnt) * 0.2;
}

struct W3 { double v[5][5][5]; };
HDC W3 w3j_calc(int l1, int l2, int l3, int p) {
    W3 out{};
    double C[5][5][5] = {};
    for (int m1 = -l1; m1 <= l1; ++m1)
        for (int m2 = -l2; m2 <= l2; ++m2)
            for (int m3 = -l3; m3 <= l3; ++m3)
                C[l1 + m1][l2 + m2][l3 + m3] = su2_cg(l1, l2, l3, m1, m2, m3);
    const Qm q1 = qmat(l1), q2 = qmat(l2), q3 = qmat(l3);
    const int d1 = 2 * l1 + 1, d2 = 2 * l2 + 1, d3 = 2 * l3 + 1;
    double Wr[5][5][5] = {}, Wi[5][5][5] = {};
    for (int j = 0; j < d1; ++j)
        for (int l = 0; l < d2; ++l)
            for (int n = 0; n < d3; ++n) {
                CD acc{0.0, 0.0};
                for (int i = 0; i < d1; ++i)
                    for (int k = 0; k < d2; ++k)
                        for (int m = 0; m < d3; ++m) {
                            const double c = C[i][k][m];
                            if (c == 0.0) continue;
                            CD t = cmul(q1.v[i][j], q2.v[k][l]);
                            t = cmul(t, CD{q3.v[m][n].re, -q3.v[m][n].im});
                            acc.re += t.re * c;
                            acc.im += t.im * c;
                        }
                Wr[j][l][n] = acc.re;
                Wi[j][l][n] = acc.im;
            }
    double nr = 0.0, ni = 0.0;
    for (int j = 0; j < d1; ++j)
        for (int l = 0; l < d2; ++l)
            for (int n = 0; n < d3; ++n) { nr += Wr[j][l][n] * Wr[j][l][n]; ni += Wi[j][l][n] * Wi[j][l][n]; }
    const bool useR = (nr >= ni);
    const double scale = path_pref(p) / csqrt(useR ? nr : ni);
    for (int j = 0; j < d1; ++j)
        for (int l = 0; l < d2; ++l)
            for (int n = 0; n < d3; ++n)
                out.v[j][l][n] = (useR ? Wr[j][l][n] : Wi[j][l][n]) * scale;
    return out;
}

template <int I, int J, int K, int P>
struct WHold { static constexpr W3 W = w3j_calc(I, J, K, P); };
template <int I, int J, int K, int P> constexpr W3 WHold<I, J, K, P>::W;

template <int N> struct Ic { static constexpr int v = N; };

template <int NA, int NB, int NC, int IDX, class Fn>
__device__ __forceinline__ void unr3(Fn&& f) {
    if constexpr (IDX < NA * NB * NC) {
        f(Ic<IDX / (NB * NC)>{}, Ic<(IDX / NC) % NB>{}, Ic<IDX % NC>{});
        unr3<NA, NB, NC, IDX + 1>(f);
    }
}

template <int I, int J, int K, int P>
__device__ __forceinline__ void apply_path(const float (&xi)[2 * I + 1],
                                           const float (&yj)[2 * J + 1],
                                           float rw,
                                           float (&ok)[2 * K + 1]) {
    unr3<2 * I + 1, 2 * J + 1, 2 * K + 1, 0>([&](auto A, auto B, auto C) {
        constexpr double wv = WHold<I, J, K, P>::W.v[decltype(A)::v][decltype(B)::v][decltype(C)::v];
        if constexpr (wv > 1e-7 || wv < -1e-7) {
            ok[decltype(C)::v] =
                fmaf((float)wv * (xi[decltype(A)::v] * yj[decltype(B)::v]), rw, ok[decltype(C)::v]);
        }
    });
}

__device__ __forceinline__ unsigned pack_half2(float lo, float hi) {
    const __half2 h = __floats2half2_rn(lo, hi);
    return *(const unsigned*)&h;
}

// ============================================================================
// Prep kernel: fp16 fragment-ordered, column-permuted copy of w2.
// ============================================================================
__global__ void prep_kernel(const float* __restrict__ w2, const float* __restrict__ b2) {
    const int idx = blockIdx.x * blockDim.x + threadIdx.x;
    if (idx < NKS * NTILES_N * 32) {
        const int l    = idx & 31;
        const int tile = idx >> 5;
        const int ks   = tile / NTILES_N;
        const int ntg  = tile % NTILES_N;
        const int tig  = l & 3;
        const int gid  = l >> 2;
        const int colp = ntg * 8 + gid;
        const int u    = colp / NPATH;
        const int t    = colp % NPATH;
        const int col  = t * F + u;
        const int k0   = ks * 16 + tig * 2;
        uint2 v;
        v.x = pack_half2(w2[(k0 + 0) * RADIAL + col], w2[(k0 + 1) * RADIAL + col]);
        v.y = pack_half2(w2[(k0 + 8) * RADIAL + col], w2[(k0 + 9) * RADIAL + col]);
        d_w2h[idx] = v;
    }
    if (idx < RADIAL) {
        const int u = idx / NPATH;
        const int t = idx % NPATH;
        d_b2p[idx] = b2[t * F + u];
    }
}

// ============================================================================
// Fused kernel: 32 edges/block, 128 threads, 6 blocks/SM.  (R12 + prefetch)
//  P1: MLP -> h_s (fp16) + geom/meta
//  per 16-edge m-tile: [prefetch TP node rows into L1]
//                      [warps mma 88-col slices -> rsl] sync
//                      [warp w TP for 4 edges, lane=channel] sync
// ============================================================================
__global__ void __launch_bounds__(128, 6)
conv_kernel(const float* __restrict__ nodes, const float* __restrict__ pos,
            const int* __restrict__ src, const int* __restrict__ dst,
            const float* __restrict__ w1, const float* __restrict__ b1,
            float* __restrict__ out) {
    __shared__ __half h_s[EPB * HSTRIDE];   // [32][72] fp16           (4608 B)
    __shared__ float rsl[4 * RSL_W];        // 4 x (16x100 + 8 skew)  (25728 B)
    __shared__ float4 geom_s[EPB];          // (ux,uy,uz,cut)           (512 B)
    __shared__ int2  meta_s[EPB];           // (src,dst)                (256 B)
    __shared__ float b2p_s[RADIAL];         //                         (1408 B)

    const int tid  = threadIdx.x;
    const int lane = tid & 31;
    const int w    = tid >> 5;
    const int eblk = blockIdx.x * EPB;

    for (int i = tid; i < RADIAL; i += 128) b2p_s[i] = d_b2p[i];

    // ------------------------------------------------------------------ P1
    constexpr float PI = 3.14159265358979323846f;
    {
        float w1a[8], w1b[8];
#pragma unroll
        for (int n = 0; n < 8; ++n) {
            w1a[n] = w1[n * HIDDEN + lane];
            w1b[n] = w1[n * HIDDEN + 32 + lane];
        }
        const float b1a = b1[lane], b1b = b1[lane + 32];

        for (int i = 0; i < EPB / 4; ++i) {       // 8 edges per warp
            const int el = w * (EPB / 4) + i;
            const int eg = eblk + el;
            if (eg < N_EDGES) {
                const int s = src[eg], d = dst[eg];
                const float dx = pos[3 * s + 0] - pos[3 * d + 0];
                const float dy = pos[3 * s + 1] - pos[3 * d + 1];
                const float dz = pos[3 * s + 2] - pos[3 * d + 2];
                const float dist = sqrtf(dx * dx + dy * dy + dz * dz);

                const float uu = dist * 0.25f;
                const float uu2 = uu * uu;
                const float uu5 = uu2 * uu2 * uu;
                const float cutv = 1.0f - 6.0f * uu5 + 5.0f * uu5 * uu;
                const float cut = (dist < 4.0f) ? cutv : 0.0f;
                const float invd = __fdividef(1.0f, fmaxf(dist, 1e-12f));
                if (lane == 0) {
                    geom_s[el] = make_float4(dx * invd, dy * invd, dz * invd, cut);
                    meta_s[el] = make_int2(s, d);
                }

                const float t = dist * 0.2f;
                float sp, cp;
                __sincosf(PI * t, &sp, &cp);
                const float mask = (t > 0.0f && t < 1.0f) ? 1.0f : 0.0f;
                const float inv_t = (t > 0.0f) ? __fdividef(1.0f, t) : 1.0f;
                const float coef = 0.6324555320336759f * inv_t * mask;
                float acc_lo = b1a, acc_hi = b1b;
                float s_prev = 0.0f, s_cur = sp;
                const float c2 = 2.0f * cp;
#pragma unroll
                for (int n = 0; n < 8; ++n) {
                    const float bn = coef * s_cur;
                    acc_lo = fmaf(bn, w1a[n], acc_lo);
                    acc_hi = fmaf(bn, w1b[n], acc_hi);
                    const float s_next = c2 * s_cur - s_prev;
                    s_prev = s_cur; s_cur = s_next;
                }
                const float hlo = __fdividef(acc_lo, 1.0f + __expf(-acc_lo));
                const float hhi = __fdividef(acc_hi, 1.0f + __expf(-acc_hi));
                h_s[el * HSTRIDE + lane]      = __float2half_rn(hlo);
                h_s[el * HSTRIDE + 32 + lane] = __float2half_rn(hhi);
            } else {
                if (lane == 0) {
                    geom_s[el] = make_float4(0.f, 0.f, 0.f, 0.f);
                    meta_s[el] = make_int2(0, 0);
                }
                h_s[el * HSTRIDE + lane]      = __float2half_rn(0.f);
                h_s[el * HSTRIDE + 32 + lane] = __float2half_rn(0.f);
            }
        }
    }
    __syncthreads();

    // ------------------------------------------------------- per-m-tile loop
    const int gid = lane >> 2, tig = lane & 3;
    const uint2* __restrict__ bswz = d_w2h;
    constexpr float S3   = 1.7320508075688772f;
    constexpr float S15  = 3.8729833462074170f;
    constexpr float S5H  = 1.1180339887498949f;
    constexpr float S15H = 1.9364916731037085f;

#pragma unroll 1
    for (int mt = 0; mt < EPB / 16; ++mt) {       // 2 m-tiles
        // ---- prefetch: warm L1 with the 4 node rows this warp will TP-gather
        //      after the mma phase (~500 cyc of cover). 1 line per lane<9.
        {
#pragma unroll
            for (int qq = 0; qq < 4; ++qq) {
                const int sa = meta_s[mt * 16 + w * 4 + qq].x;
                if (lane < 9) {
                    const float* p = nodes + (size_t)sa * FEAT + lane * 32;
                    asm volatile("prefetch.global.L1 [%0];" :: "l"(p) : "memory");
                }
            }
        }

        // ---- mma: warp w -> cols 88w..88w+87 of rows mt*16..mt*16+15
        {
            float* rslw = rsl + w * RSL_W;
            const int r0 = mt * 16 + gid;
            unsigned afr[NKS][4];
#pragma unroll
            for (int ks = 0; ks < NKS; ++ks) {
                const int k0 = ks * 16 + tig * 2;
                afr[ks][0] = *(const unsigned*)&h_s[r0 * HSTRIDE + k0];
                afr[ks][1] = *(const unsigned*)&h_s[(r0 + 8) * HSTRIDE + k0];
                afr[ks][2] = *(const unsigned*)&h_s[r0 * HSTRIDE + k0 + 8];
                afr[ks][3] = *(const unsigned*)&h_s[(r0 + 8) * HSTRIDE + k0 + 8];
            }
#pragma unroll 2
            for (int nt = 0; nt < 11; ++nt) {
                const int ntg = 11 * w + nt;
                float d0 = 0.f, d1 = 0.f, d2 = 0.f, d3 = 0.f;
#pragma unroll
                for (int ks = 0; ks < NKS; ++ks) {
                    const uint2 bb = bswz[(ks * NTILES_N + ntg) * 32 + lane];  // coalesced 256B
                    asm volatile(
                        "mma.sync.aligned.m16n8k16.row.col.f32.f16.f16.f32 "
                        "{%0,%1,%2,%3}, {%4,%5,%6,%7}, {%8,%9}, {%0,%1,%2,%3};"
                        : "+f"(d0), "+f"(d1), "+f"(d2), "+f"(d3)
                        : "r"(afr[ks][0]), "r"(afr[ks][1]), "r"(afr[ks][2]), "r"(afr[ks][3]),
                          "r"(bb.x), "r"(bb.y));
                }
                const int c0 = nt * 8 + 2 * tig;
                *(float2*)&rslw[gid * 100 + c0]       = make_float2(d0, d1);
                *(float2*)&rslw[(gid + 8) * 100 + c0] = make_float2(d2, d3);
            }
        }
        __syncthreads();

        // ---- TP: warp w handles edges r = w*4 .. w*4+3 of this tile; lane = channel u
        {
            const int uw = lane >> 3;               // source warp slice
            const int ubase = (lane & 7) * NPATH;   // col within slice
#pragma unroll 1
            for (int qq = 0; qq < 4; ++qq) {
                const int r  = w * 4 + qq;
                const int eg = eblk + mt * 16 + r;
                if (eg < N_EDGES) {
                    const float4 gm = geom_s[mt * 16 + r];
                    const int2 sd = meta_s[mt * 16 + r];
                    const float ux = gm.x, uy = gm.y, uz = gm.z, cut = gm.w;

                    float y0[1] = { 1.0f };
                    float y1[3] = { S3 * uy, S3 * uz, S3 * ux };
                    float y2[5] = { S15 * ux * uy, S15 * uy * uz, S5H * (3.0f * uz * uz - 1.0f),
                                    S15 * ux * uz, S15H * (ux * ux - uy * uy) };

                    const float* rsrc = rsl + uw * RSL_W + r * 100 + ubase;
                    float rw[NPATH];
#pragma unroll
                    for (int t = 0; t < NPATH; ++t)
                        rw[t] = (rsrc[t] + b2p_s[lane * NPATH + t]) * cut;

                    const float* nb = nodes + sd.x * FEAT;
                    float x0[1] = { nb[lane] };
                    float x1[3], x2[5];
#pragma unroll
                    for (int a = 0; a < 3; ++a) x1[a] = nb[32 + 3 * lane + a];
#pragma unroll
                    for (int a = 0; a < 5; ++a) x2[a] = nb[128 + 5 * lane + a];

                    float o0[1] = {0.0f};
                    float o1[3] = {0.0f, 0.0f, 0.0f};
                    float o2[5] = {0.0f, 0.0f, 0.0f, 0.0f, 0.0f};
                    apply_path<0, 0, 0, 0>(x0, y0, rw[0], o0);
                    apply_path<0, 1, 1, 1>(x0, y1, rw[1], o1);
                    apply_path<0, 2, 2, 2>(x0, y2, rw[2], o2);
                    apply_path<1, 0, 1, 3>(x1, y0, rw[3], o1);
                    apply_path<1, 1, 0, 4>(x1, y1, rw[4], o0);
                    apply_path<1, 1, 2, 5>(x1, y1, rw[5], o2);
                    apply_path<1, 2, 1, 6>(x1, y2, rw[6], o1);
                    apply_path<2, 0, 2, 7>(x2, y0, rw[7], o2);
                    apply_path<2, 1, 1, 8>(x2, y1, rw[8], o1);
                    apply_path<2, 2, 0, 9>(x2, y2, rw[9], o0);
                    apply_path<2, 2, 2, 10>(x2, y2, rw[10], o2);

                    float* ob = out + sd.y * FEAT;
                    atomicAdd(ob + lane, o0[0]);
#pragma unroll
                    for (int c = 0; c < 3; ++c) atomicAdd(ob + 32 + 3 * lane + c, o1[c]);
#pragma unroll
                    for (int c = 0; c < 5; ++c) atomicAdd(ob + 128 + 5 * lane + c, o2[c]);
                }
            }
        }
        __syncthreads();   // rsl consumed before next tile's mma overwrites it
    }
}

// ============================================================================
// Launch: memset out, prep, fused kernel. All graph-capturable; no allocation.
// ============================================================================
extern "C" void kernel_launch(void* const* d_in, const int* in_sizes, int n_in,
                              void* d_out, int out_size) {
    (void)in_sizes; (void)n_in;
    const float* nodes = (const float*)d_in[0];
    const float* pos   = (const float*)d_in[1];
    const int*   src   = (const int*)d_in[2];
    const int*   dst   = (const int*)d_in[3];
    const float* w1    = (const float*)d_in[4];
    const float* b1    = (const float*)d_in[5];
    const float* w2    = (const float*)d_in[6];
    const float* b2    = (const float*)d_in[7];
    float* out = (float*)d_out;

    cudaMemsetAsync(out, 0, (size_t)out_size * sizeof(float), 0);

    const int prep_n = NKS * NTILES_N * 32;
    prep_kernel<<<(prep_n + 127) / 128, 128>>>(w2, b2);

    conv_kernel<<<NBLK, 128>>>(nodes, pos, src, dst, w1, b1, out);
}